// round 11
// baseline (speedup 1.0000x reference)
#include <cuda_runtime.h>
#include <cuda_fp16.h>
#include <cstdint>

// ---------------------------------------------------------------------------
// Problem constants
// ---------------------------------------------------------------------------
#define B_SZ   8192
#define IN_SZ  512
#define OUT_SZ 512
#define GP1    21             // grid_size + 1 coefficients per (o,i)
#define KPI    24             // k-slots per feature (21 coeff + base + 2 pad; 4-aligned)
#define KTOT   (IN_SZ * KPI)  // 12288 logical K
#define STAGES (KTOT / 64)    // 192 stages of logical K=64 (2 sparse k-steps)

// Sparse-GEMM reformulation: out[b,o] = sum_k A[b,k] * Cmat[o,k], k = i*24+j.
// A row nonzeros per feature: (idx: 1-t), (idx+1: t), (21: silu).  Every
// 4-aligned group has <=2 nonzeros -> A is exactly 2:4 sparse.
// mma.sp::ordered_metadata.m16n8k32: half the instruction count of dense
// m16n8k16 at the measured HMMA issue ceiling.
// Metadata layout (PTX ISA, m16n8k32 f16, selector 0): threads T(4q), T(4q+1)
// both cover rows q (bits 0-15) and q+8 (bits 16-31); T(4q) holds k0-15,
// T(4q+1) holds k16-31.  (R9 used full-word-per-row mapping -> rel_err 0.57.)

// ---------------------------------------------------------------------------
// Device scratch (static)
// ---------------------------------------------------------------------------
__device__ __half g_Cmat[(size_t)OUT_SZ * KTOT];   // [o][k], 12.6 MB
__device__ float2 g_P[(size_t)IN_SZ * B_SZ];       // [i][b] : {silu(xc), u}

// ---------------------------------------------------------------------------
// Helpers
// ---------------------------------------------------------------------------
__device__ __forceinline__ uint32_t smem_u32(const void* p) {
    uint32_t a;
    asm("{ .reg .u64 t; cvta.to.shared.u64 t, %1; cvt.u32.u64 %0, t; }" : "=r"(a) : "l"(p));
    return a;
}
__device__ __forceinline__ uint32_t sw128(uint32_t off) { return off ^ ((off >> 3) & 0x70); }

__device__ __forceinline__ void ldsm_x4(uint32_t addr, uint32_t r[4]) {
    asm volatile("ldmatrix.sync.aligned.m8n8.x4.shared.b16 {%0,%1,%2,%3}, [%4];"
                 : "=r"(r[0]), "=r"(r[1]), "=r"(r[2]), "=r"(r[3]) : "r"(addr));
}
// Sparse MMA: D[16x8] f32 += A_sp[16x32 2:4] * B[32x8], metadata e, selector 0.
__device__ __forceinline__ void mma_sp(float d[4], const uint32_t a[4],
                                       uint32_t b0, uint32_t b1, uint32_t b2, uint32_t b3,
                                       uint32_t e) {
    asm volatile("mma.sp::ordered_metadata.sync.aligned.m16n8k32.row.col.f32.f16.f16.f32 "
                 "{%0,%1,%2,%3}, {%4,%5,%6,%7}, {%8,%9,%10,%11}, {%0,%1,%2,%3}, %12, 0x0;"
                 : "+f"(d[0]), "+f"(d[1]), "+f"(d[2]), "+f"(d[3])
                 : "r"(a[0]), "r"(a[1]), "r"(a[2]), "r"(a[3]),
                   "r"(b0), "r"(b1), "r"(b2), "r"(b3), "r"(e));
}
__device__ __forceinline__ uint32_t pack2(float lo, float hi) {
    return (uint32_t)__half_as_ushort(__float2half_rn(lo))
         | ((uint32_t)__half_as_ushort(__float2half_rn(hi)) << 16);
}

// ---------------------------------------------------------------------------
// Kernel 1: per-(b,i) params, i-major.  u = (clip(x)+1)*10 in [0,20].
// ---------------------------------------------------------------------------
__global__ void kan_params(const float* __restrict__ x) {
    __shared__ float tile[32][33];
    const int b0 = blockIdx.x * 32;
    const int i0 = blockIdx.y * 32;
    const int tx = threadIdx.x & 31;
    const int ty = threadIdx.x >> 5;
#pragma unroll
    for (int r = ty; r < 32; r += 8)
        tile[r][tx] = x[(size_t)(b0 + r) * IN_SZ + i0 + tx];
    __syncthreads();
#pragma unroll
    for (int r = ty; r < 32; r += 8) {
        float xv = tile[tx][r];
        float xc = fminf(1.0f, fmaxf(-1.0f, xv));
        float s  = xc / (1.0f + __expf(-xc));
        float u  = (xc + 1.0f) * 10.0f;
        g_P[(size_t)(i0 + r) * B_SZ + b0 + tx] = make_float2(s, u);
    }
}

// ---------------------------------------------------------------------------
// Kernel 2: build Cmat fp16 [o][12288]; slots 22,23 zero (never selected).
// ---------------------------------------------------------------------------
__global__ void kan_cmat(const float* __restrict__ coeffs, const float* __restrict__ bw) {
    int g = blockIdx.x * 256 + threadIdx.x;   // [0, 512*512)
    int o = g >> 9, i = g & 511;
    const float* c = coeffs + (size_t)o * (IN_SZ * GP1) + (size_t)i * GP1;
    __half h[KPI];
#pragma unroll
    for (int j = 0; j < GP1; j++) h[j] = __float2half_rn(c[j]);
    h[21] = __float2half_rn(bw[(size_t)o * IN_SZ + i]);
    h[22] = __ushort_as_half((unsigned short)0);
    h[23] = __ushort_as_half((unsigned short)0);
    uint4* dst = (uint4*)(g_Cmat + (size_t)o * KTOT + (size_t)i * KPI);
    const uint4* src = (const uint4*)h;
#pragma unroll
    for (int v = 0; v < 3; v++) dst[v] = src[v];
}

// ---------------------------------------------------------------------------
// Main sparse GEMM: 256 CTAs (64 b x 4 o), CTA tile 128x128, 8 warps,
// warp tile 64x32.  Stage = logical K 64 = 2 sparse k-steps, double buffered.
// SMEM: Acomp[2][128 rows x 128B] (64B data) @0, B[2][128x128B] @32768,
// meta[2][128 rows x 8B] @65536 -> 67584 B, 2 CTAs/SM.
// ---------------------------------------------------------------------------
#define A_REG   0
#define B_REG   32768
#define M_REG   65536
#define SMEM_SZ 67584

// A-gen (threads 0-127): row = one b.  Build compressed values (1 u32 = 2
// stored halves per 4-group) + canonical per-row metadata nibbles (bit 4g =
// group g's index pair, first index in low 2 bits) fully in registers.
__device__ __forceinline__ void genA(uint32_t sb, char* smem, int buf, int stage,
                                     int bb, int row) {
    uint32_t vals[16];
#pragma unroll
    for (int g = 0; g < 16; g++) vals[g] = 0u;
    uint32_t nib0 = 0x44444444u, nib1 = 0x44444444u;   // default indices (0,1)

    const int k0   = stage * 64;
    const int i_lo = k0 / KPI;
#pragma unroll
    for (int f = 0; f < 4; f++) {
        int i = i_lo + f;
        if (i < IN_SZ) {
            float2 pv = g_P[(size_t)i * B_SZ + bb + row];   // coalesced
            int idx = (int)pv.y;
            idx = idx > 19 ? 19 : idx;
            float t = pv.y - (float)idx;
            const int gbase = i * 6 - stage * 16;           // (i*KPI - k0)/4
            const int gi = idx >> 2, ip = idx & 3;

            // group 5: slots {20,21,22,23}; kept = (20: t if idx==19 else 0, 21: silu)
            int g5 = gbase + 5;
            if ((unsigned)g5 < 16u)
                vals[g5] = pack2(idx == 19 ? t : 0.0f, pv.x);   // nib stays (0,1)

            if (ip < 3) {
                int g = gbase + gi;                    // both 1-t and t in one group
                if ((unsigned)g < 16u) {
                    vals[g] = pack2(1.0f - t, t);
                    uint32_t nv = (uint32_t)(ip | ((ip + 1) << 2));
                    uint32_t sh = (uint32_t)(g & 7) * 4;
                    if (g < 8) nib0 = (nib0 & ~(0xFu << sh)) | (nv << sh);
                    else       nib1 = (nib1 & ~(0xFu << sh)) | (nv << sh);
                }
            } else {                                   // ip == 3: split across groups
                int g = gbase + gi;                    // 1-t at pos 3 -> indices (2,3)
                if ((unsigned)g < 16u) {
                    vals[g] = pack2(0.0f, 1.0f - t);
                    uint32_t sh = (uint32_t)(g & 7) * 4;
                    if (g < 8) nib0 = (nib0 & ~(0xFu << sh)) | (0xEu << sh);
                    else       nib1 = (nib1 & ~(0xFu << sh)) | (0xEu << sh);
                }
                if (gi + 1 < 5) {                      // t at pos 0 of next group
                    int g2 = gbase + gi + 1;           // (gi+1==5 handled by g5)
                    if ((unsigned)g2 < 16u)
                        vals[g2] = pack2(t, 0.0f);     // nib stays (0,1)
                }
            }
        }
    }

    // store compressed row (64B data in 128B sw128 row) + metadata (8B)
    char* arow = smem + A_REG + buf * 16384;
    const uint32_t rowoff = (uint32_t)row * 128;
#pragma unroll
    for (int c = 0; c < 4; c++)
        *(uint4*)(arow + sw128(rowoff + c * 16)) =
            make_uint4(vals[c * 4], vals[c * 4 + 1], vals[c * 4 + 2], vals[c * 4 + 3]);
    *(uint2*)(smem + M_REG + (size_t)(buf * 128 + row) * 8) = make_uint2(nib0, nib1);
}

// B-load (threads 128-255): 128 rows x 128B per stage via cp.async.
__device__ __forceinline__ void loadB(uint32_t sb, int buf, int stage, int ob, int t2) {
    const int k0 = stage * 64;
#pragma unroll
    for (int rep = 0; rep < 8; rep++) {
        int q = t2 + rep * 128;
        int r = q >> 3;
        int c = q & 7;
        const __half* gp = g_Cmat + (size_t)(ob + r) * KTOT + (k0 + c * 8);
        uint32_t sa = sb + B_REG + buf * 16384 + sw128((uint32_t)r * 128 + (uint32_t)c * 16);
        asm volatile("cp.async.cg.shared.global [%0], [%1], 16;" :: "r"(sa), "l"(gp));
    }
}

__global__ __launch_bounds__(256, 2) void kan_main(float* __restrict__ out) {
    extern __shared__ char smem[];
    uint32_t sb = smem_u32(smem);
    const int tid   = threadIdx.x;
    const int lane  = tid & 31;
    const int wid   = tid >> 5;
    const int warpM = wid >> 2;             // 0..1 -> 64-row b stripe
    const int warpN = wid & 3;              // 0..3 -> 32-col o stripe
    const int ob = blockIdx.x * 128, bb = blockIdx.y * 128;

    float acc[4][4][4];
#pragma unroll
    for (int mt = 0; mt < 4; mt++)
#pragma unroll
        for (int nt = 0; nt < 4; nt++)
#pragma unroll
            for (int v = 0; v < 4; v++) acc[mt][nt][v] = 0.f;

    const uint32_t lrow = lane & 15;
    const uint32_t lkb  = (lane >> 4) * 16;
    const uint32_t mq    = (uint32_t)(lane >> 2);   // quad id -> row pair (mq, mq+8)
    const uint32_t khalf = (uint32_t)(lane & 1);    // 0: k0-15, 1: k16-31

    if (tid < 128) genA(sb, smem, 0, 0, bb, tid);
    else           loadB(sb, 0, 0, ob, tid - 128);
    asm volatile("cp.async.commit_group;");

    for (int s = 0; s < STAGES; s++) {
        const int cb = s & 1, nb = cb ^ 1;
        if (s + 1 < STAGES) {
            if (tid < 128) genA(sb, smem, nb, s + 1, bb, tid);
            else           loadB(sb, nb, s + 1, ob, tid - 128);
            asm volatile("cp.async.commit_group;");
            asm volatile("cp.async.wait_group 1;");
        } else {
            asm volatile("cp.async.wait_group 0;");
        }
        __syncthreads();

        const uint32_t Ab = sb + A_REG + cb * 16384;
        const uint32_t Bb = sb + B_REG + cb * 16384;
        const uint32_t Mb = sb + M_REG + cb * 1024;
#pragma unroll
        for (int ks = 0; ks < 2; ks++) {                 // 2 sparse k-steps (K=32 each)
            uint32_t a[4][4], e[4];
#pragma unroll
            for (int mt = 0; mt < 4; mt++) {
                uint32_t row0 = (uint32_t)(warpM * 64 + mt * 16);
                ldsm_x4(Ab + sw128((row0 + lrow) * 128 + ks * 32 + lkb), a[mt]);
                // metadata: row q -> bits 0-15, row q+8 -> bits 16-31;
                // lane 4q holds k0-15 nibbles, lane 4q+1 holds k16-31.
                uint32_t w0, w1;
                asm volatile("ld.shared.b32 %0, [%1];"
                             : "=r"(w0) : "r"(Mb + (row0 + mq) * 8 + (uint32_t)ks * 4));
                asm volatile("ld.shared.b32 %0, [%1];"
                             : "=r"(w1) : "r"(Mb + (row0 + mq + 8) * 8 + (uint32_t)ks * 4));
                uint32_t h0 = khalf ? (w0 >> 16) : (w0 & 0xFFFFu);
                uint32_t h1 = khalf ? (w1 >> 16) : (w1 & 0xFFFFu);
                e[mt] = h0 | (h1 << 16);
            }
            uint32_t bl[2][4], bh[2][4];
#pragma unroll
            for (int bt = 0; bt < 2; bt++) {
                uint32_t nrow = (uint32_t)(warpN * 32 + bt * 16) + lrow;
                ldsm_x4(Bb + sw128(nrow * 128 + ks * 64 + lkb),      bl[bt]); // k0-15
                ldsm_x4(Bb + sw128(nrow * 128 + ks * 64 + 32 + lkb), bh[bt]); // k16-31
            }
#pragma unroll
            for (int mt = 0; mt < 4; mt++)
#pragma unroll
                for (int nt = 0; nt < 4; nt++) {
                    int bt = nt >> 1, hi = nt & 1;
                    mma_sp(acc[mt][nt], a[mt],
                           bl[bt][hi], bl[bt][hi + 2], bh[bt][hi], bh[bt][hi + 2],
                           e[mt]);
                }
        }
        __syncthreads();
    }

    // epilogue
#pragma unroll
    for (int mt = 0; mt < 4; mt++) {
        int r0 = bb + warpM * 64 + mt * 16 + (lane >> 2);
#pragma unroll
        for (int nt = 0; nt < 4; nt++) {
            int c0 = ob + warpN * 32 + nt * 8 + (lane & 3) * 2;
            *(float2*)&out[(size_t)r0 * OUT_SZ + c0] =
                make_float2(acc[mt][nt][0], acc[mt][nt][1]);
            *(float2*)&out[(size_t)(r0 + 8) * OUT_SZ + c0] =
                make_float2(acc[mt][nt][2], acc[mt][nt][3]);
        }
    }
}

// ---------------------------------------------------------------------------
// Launch
// ---------------------------------------------------------------------------
extern "C" void kernel_launch(void* const* d_in, const int* in_sizes, int n_in,
                              void* d_out, int out_size) {
    const float* x      = (const float*)d_in[0];
    const float* coeffs = (const float*)d_in[1];
    const float* base_w = (const float*)d_in[2];
    float* out = (float*)d_out;

    cudaFuncSetAttribute(kan_main, cudaFuncAttributeMaxDynamicSharedMemorySize, SMEM_SZ);

    kan_params<<<dim3(B_SZ / 32, IN_SZ / 32), 256>>>(x);
    kan_cmat  <<<(OUT_SZ * IN_SZ) / 256, 256>>>(coeffs, base_w);
    kan_main  <<<dim3(OUT_SZ / 128, B_SZ / 128), 256, SMEM_SZ>>>(out);
}

// round 12
// speedup vs baseline: 2.4415x; 2.4415x over previous
#include <cuda_runtime.h>
#include <cuda_fp16.h>
#include <cstdint>

// ---------------------------------------------------------------------------
// Problem constants
// ---------------------------------------------------------------------------
#define B_SZ   8192
#define IN_SZ  512
#define OUT_SZ 512
#define GP1    21            // grid_size + 1 coefficients per (o,i)
#define KPI    22            // k-slots per input feature (21 coeff + base)
#define KTOT   (IN_SZ * KPI) // 11264
#define STAGES (KTOT / 64)   // 176 stages of K=64

// Dense-GEMM reformulation (fastest verified path; sparse mma.sp measured 2.2x
// SLOWER on sm_103 legacy tensor pipe):
//   out[b,o] = sum_k A[b,k] * Cmat[o,k],   k = i*22 + j
//   A[b, i*22+j]   = (j==idx: 1-t), (j==idx+1: t), (j==21: silu(xc)), else 0  (fp16)
//   Cmat[o, i*22+j]= (j<21: coeffs[o,i,j]), (j==21: base_w[o,i])               (fp16)
// fp32 accumulation via mma.sync m16n8k16; measured ~94% of the ~273 TF/s
// legacy HMMA ceiling. This round removes barrier + launch overheads.

// ---------------------------------------------------------------------------
// Device scratch (static)
// ---------------------------------------------------------------------------
__device__ __half g_Cmat[(size_t)OUT_SZ * KTOT];   // [o][k], 11.5 MB
__device__ float2 g_P[(size_t)IN_SZ * B_SZ];       // [i][b] : {silu(xc), u}

// ---------------------------------------------------------------------------
// Helpers
// ---------------------------------------------------------------------------
__device__ __forceinline__ uint32_t smem_u32(const void* p) {
    uint32_t a;
    asm("{ .reg .u64 t; cvta.to.shared.u64 t, %1; cvt.u32.u64 %0, t; }" : "=r"(a) : "l"(p));
    return a;
}
__device__ __forceinline__ uint32_t sw128(uint32_t off) { return off ^ ((off >> 3) & 0x70); }

__device__ __forceinline__ void ldsm_x4(uint32_t addr, uint32_t r[4]) {
    asm volatile("ldmatrix.sync.aligned.m8n8.x4.shared.b16 {%0,%1,%2,%3}, [%4];"
                 : "=r"(r[0]), "=r"(r[1]), "=r"(r[2]), "=r"(r[3]) : "r"(addr));
}
__device__ __forceinline__ void mma16816(float d[4], const uint32_t a[4],
                                         uint32_t b0, uint32_t b1) {
    asm volatile("mma.sync.aligned.m16n8k16.row.col.f32.f16.f16.f32 "
                 "{%0,%1,%2,%3}, {%4,%5,%6,%7}, {%8,%9}, {%0,%1,%2,%3};"
                 : "+f"(d[0]), "+f"(d[1]), "+f"(d[2]), "+f"(d[3])
                 : "r"(a[0]), "r"(a[1]), "r"(a[2]), "r"(a[3]), "r"(b0), "r"(b1));
}

// ---------------------------------------------------------------------------
// Prep kernel: fuses params (blocks [0,4096)) and Cmat build (blocks >= 4096)
// so both run concurrently in a single launch.
// ---------------------------------------------------------------------------
#define PARAM_BLOCKS 4096                       // (B/32)*(IN/32) = 256*16
#define CMAT_BLOCKS  (OUT_SZ * (KTOT / 8) / 256)  // 512*1408/256 = 2816

__global__ void kan_prep(const float* __restrict__ x,
                         const float* __restrict__ coeffs,
                         const float* __restrict__ bw) {
    if (blockIdx.x < PARAM_BLOCKS) {
        // ---- params: per-(b,i), i-major.  u = (clip(x)+1)*10 in [0,20]. ----
        __shared__ float tile[32][33];
        const int pb = blockIdx.x;
        const int b0 = (pb & 255) * 32;
        const int i0 = (pb >> 8) * 32;
        const int tx = threadIdx.x & 31;
        const int ty = threadIdx.x >> 5;
#pragma unroll
        for (int r = ty; r < 32; r += 8)
            tile[r][tx] = x[(size_t)(b0 + r) * IN_SZ + i0 + tx];
        __syncthreads();
#pragma unroll
        for (int r = ty; r < 32; r += 8) {
            float xv = tile[tx][r];
            float xc = fminf(1.0f, fmaxf(-1.0f, xv));
            float s  = xc / (1.0f + __expf(-xc));
            float u  = (xc + 1.0f) * 10.0f;
            g_P[(size_t)(i0 + r) * B_SZ + b0 + tx] = make_float2(s, u);
        }
    } else {
        // ---- Cmat fp16 [o][11264], k-linear 16B chunks ----
        int gch = (blockIdx.x - PARAM_BLOCKS) * 256 + threadIdx.x;
        int o  = gch / (KTOT / 8);
        int ch = gch - o * (KTOT / 8);
        int k0 = ch * 8;
        __half h[8];
#pragma unroll
        for (int v = 0; v < 8; v++) {
            int k = k0 + v;
            int i = k / KPI;
            int j = k - i * KPI;
            float val = (j < GP1) ? coeffs[(size_t)o * (IN_SZ * GP1) + (size_t)i * GP1 + j]
                                  : bw[(size_t)o * IN_SZ + i];
            h[v] = __float2half_rn(val);
        }
        *(uint4*)(g_Cmat + (size_t)o * KTOT + k0) = *(const uint4*)h;
    }
}

// ---------------------------------------------------------------------------
// Main GEMM: 256 CTAs (64 b x 4 o), CTA tile 128x128, 8 warps (256 thr),
// warp tile 64x32. Stage K=64, double buffered, ONE barrier per stage:
//   iter s: wait_group 0 (cb B loaded) ; bar ; producers fill nb ; all MMA cb.
// WAR on nb (read at s-1) is separated by this iteration's barrier; WAR on
// cb writes (s-1, pre-bar) vs reads (s, post-bar) likewise.
// SMEM: A[2][128x128B] @0, B[2][128x128B] @32768 -> 64 KB, 2 CTAs/SM.
// ---------------------------------------------------------------------------
__device__ __forceinline__ void genA(char* smem, int buf, int stage, int bb, int row) {
    char* tile = smem + buf * 16384;
    const uint32_t rowoff = (uint32_t)row * 128;
    uint4 z = make_uint4(0, 0, 0, 0);
#pragma unroll
    for (int c = 0; c < 8; c++)
        *(uint4*)(tile + sw128(rowoff + c * 16)) = z;

    const int k0   = stage * 64;
    const int i_lo = k0 / KPI;
#pragma unroll
    for (int f = 0; f < 4; f++) {
        int i = i_lo + f;
        if (i < IN_SZ) {
            float2 pv = g_P[(size_t)i * B_SZ + bb + row];    // coalesced
            int idx = (int)pv.y;                             // u >= 0
            idx = idx > 19 ? 19 : idx;                       // u==20 -> idx=19, t=1
            float t = pv.y - (float)idx;
            int kbase = i * KPI - k0;                        // stage-local slot 0
            int k1 = kbase + idx;                            // 1-t
            int k2 = k1 + 1;                                 // t
            int k3 = kbase + 21;                             // silu
            if ((unsigned)k1 < 64u)
                *(__half*)(tile + sw128(rowoff + (uint32_t)k1 * 2)) = __float2half_rn(1.0f - t);
            if ((unsigned)k2 < 64u)
                *(__half*)(tile + sw128(rowoff + (uint32_t)k2 * 2)) = __float2half_rn(t);
            if ((unsigned)k3 < 64u)
                *(__half*)(tile + sw128(rowoff + (uint32_t)k3 * 2)) = __float2half_rn(pv.x);
        }
    }
}

__device__ __forceinline__ void loadB(uint32_t sb, int buf, int stage, int ob, int t2) {
    const int k0 = stage * 64;
#pragma unroll
    for (int rep = 0; rep < 8; rep++) {
        int q = t2 + rep * 128;             // [0,1024): 128 rows x 8 chunks of 16B
        int r = q >> 3;
        int c = q & 7;
        const __half* gp = g_Cmat + (size_t)(ob + r) * KTOT + (k0 + c * 8);
        uint32_t sa = sb + 32768 + buf * 16384 + sw128((uint32_t)r * 128 + (uint32_t)c * 16);
        asm volatile("cp.async.cg.shared.global [%0], [%1], 16;" :: "r"(sa), "l"(gp));
    }
}

__global__ __launch_bounds__(256, 2) void kan_main(float* __restrict__ out) {
    extern __shared__ char smem[];
    uint32_t sb = smem_u32(smem);
    const int tid   = threadIdx.x;
    const int lane  = tid & 31;
    const int wid   = tid >> 5;
    const int warpM = wid >> 2;             // 0..1 -> 64-row b stripe
    const int warpN = wid & 3;              // 0..3 -> 32-col o stripe
    const int ob = blockIdx.x * 128, bb = blockIdx.y * 128;

    float acc[4][4][4];                     // [mtile 16r][ntile 8c][reg]
#pragma unroll
    for (int mt = 0; mt < 4; mt++)
#pragma unroll
        for (int nt = 0; nt < 4; nt++)
#pragma unroll
            for (int v = 0; v < 4; v++) acc[mt][nt][v] = 0.f;

    const uint32_t lrow = lane & 15;
    const uint32_t lkb  = (lane >> 4) * 16;

    // prologue: stage 0 into buffer 0
    if (tid < 128) genA(smem, 0, 0, bb, tid);
    else           loadB(sb, 0, 0, ob, tid - 128);
    asm volatile("cp.async.commit_group;");

    for (int s = 0; s < STAGES; s++) {
        const int cb = s & 1, nb = cb ^ 1;

        asm volatile("cp.async.wait_group 0;");   // cb's B complete (issued @ s-1)
        __syncthreads();                          // cb visible; nb reads (s-1) done

        if (s + 1 < STAGES) {                     // producers fill nb for next stage
            if (tid < 128) genA(smem, nb, s + 1, bb, tid);
            else           loadB(sb, nb, s + 1, ob, tid - 128);
            asm volatile("cp.async.commit_group;");
        }

        const uint32_t Ab = sb + cb * 16384;
        const uint32_t Bb = sb + 32768 + cb * 16384;
#pragma unroll
        for (int ks = 0; ks < 4; ks++) {
            uint32_t a[4][4];
#pragma unroll
            for (int mt = 0; mt < 4; mt++) {
                uint32_t row = (uint32_t)(warpM * 64 + mt * 16) + lrow;
                ldsm_x4(Ab + sw128(row * 128 + ks * 32 + lkb), a[mt]);
            }
            uint32_t bf[2][4];
#pragma unroll
            for (int bt = 0; bt < 2; bt++) {
                uint32_t nrow = (uint32_t)(warpN * 32 + bt * 16) + lrow;
                ldsm_x4(Bb + sw128(nrow * 128 + ks * 32 + lkb), bf[bt]);
            }
#pragma unroll
            for (int mt = 0; mt < 4; mt++)
#pragma unroll
                for (int nt = 0; nt < 4; nt++) {
                    int bt = nt >> 1, hi = nt & 1;
                    mma16816(acc[mt][nt], a[mt], bf[bt][hi], bf[bt][hi + 2]);
                }
        }
    }

    // epilogue: direct f32 stores
#pragma unroll
    for (int mt = 0; mt < 4; mt++) {
        int r0 = bb + warpM * 64 + mt * 16 + (lane >> 2);
#pragma unroll
        for (int nt = 0; nt < 4; nt++) {
            int c0 = ob + warpN * 32 + nt * 8 + (lane & 3) * 2;
            *(float2*)&out[(size_t)r0 * OUT_SZ + c0] =
                make_float2(acc[mt][nt][0], acc[mt][nt][1]);
            *(float2*)&out[(size_t)(r0 + 8) * OUT_SZ + c0] =
                make_float2(acc[mt][nt][2], acc[mt][nt][3]);
        }
    }
}

// ---------------------------------------------------------------------------
// Launch: x [8192,512], coeffs [512,512,21], base_w [512,512] -> out f32 [8192,512]
// ---------------------------------------------------------------------------
extern "C" void kernel_launch(void* const* d_in, const int* in_sizes, int n_in,
                              void* d_out, int out_size) {
    const float* x      = (const float*)d_in[0];
    const float* coeffs = (const float*)d_in[1];
    const float* base_w = (const float*)d_in[2];
    float* out = (float*)d_out;

    cudaFuncSetAttribute(kan_main, cudaFuncAttributeMaxDynamicSharedMemorySize, 65536);

    kan_prep<<<PARAM_BLOCKS + CMAT_BLOCKS, 256>>>(x, coeffs, base_w);
    kan_main<<<dim3(OUT_SZ / 128, B_SZ / 128), 256, 65536>>>(out);
}

// round 14
// speedup vs baseline: 2.4427x; 1.0005x over previous
#include <cuda_runtime.h>
#include <cuda_fp16.h>
#include <cstdint>

// ---------------------------------------------------------------------------
// Problem constants
// ---------------------------------------------------------------------------
#define B_SZ   8192
#define IN_SZ  512
#define OUT_SZ 512
#define GP1    21            // grid_size + 1 coefficients per (o,i)
#define KPI    22            // k-slots per input feature (21 coeff + base)
#define KTOT   (IN_SZ * KPI) // 11264
#define STAGES (KTOT / 64)   // 176 stages of K=64

// Dense-GEMM reformulation:
//   out[b,o] = sum_k A[b,k] * Cmat[o,k],   k = i*22 + j
//   A[b, i*22+j]   = (j==idx: 1-t), (j==idx+1: t), (j==21: silu(xc)), else 0  (fp16)
//   Cmat[o, i*22+j]= (j<21: coeffs[o,i,j]), (j==21: base_w[o,i])               (fp16)
// R12: params prefetched into an SMEM ring via cp.async (distance 2) so genA
// does LDS instead of LDG — removes L2-latency stalls from MMA warps.

// ---------------------------------------------------------------------------
// Device scratch (static)
// ---------------------------------------------------------------------------
__device__ __half g_Cmat[(size_t)OUT_SZ * KTOT];   // [o][k], 11.5 MB
__device__ float2 g_P[(size_t)IN_SZ * B_SZ];       // [i][b] : {silu(xc), u}

// ---------------------------------------------------------------------------
// Helpers
// ---------------------------------------------------------------------------
__device__ __forceinline__ uint32_t smem_u32(const void* p) {
    uint32_t a;
    asm("{ .reg .u64 t; cvta.to.shared.u64 t, %1; cvt.u32.u64 %0, t; }" : "=r"(a) : "l"(p));
    return a;
}
__device__ __forceinline__ uint32_t sw128(uint32_t off) { return off ^ ((off >> 3) & 0x70); }

__device__ __forceinline__ void ldsm_x4(uint32_t addr, uint32_t r[4]) {
    asm volatile("ldmatrix.sync.aligned.m8n8.x4.shared.b16 {%0,%1,%2,%3}, [%4];"
                 : "=r"(r[0]), "=r"(r[1]), "=r"(r[2]), "=r"(r[3]) : "r"(addr));
}
__device__ __forceinline__ void mma16816(float d[4], const uint32_t a[4],
                                         uint32_t b0, uint32_t b1) {
    asm volatile("mma.sync.aligned.m16n8k16.row.col.f32.f16.f16.f32 "
                 "{%0,%1,%2,%3}, {%4,%5,%6,%7}, {%8,%9}, {%0,%1,%2,%3};"
                 : "+f"(d[0]), "+f"(d[1]), "+f"(d[2]), "+f"(d[3])
                 : "r"(a[0]), "r"(a[1]), "r"(a[2]), "r"(a[3]), "r"(b0), "r"(b1));
}

// ---------------------------------------------------------------------------
// Prep kernel: fuses params (blocks [0,4096)) and Cmat build (blocks >= 4096).
// ---------------------------------------------------------------------------
#define PARAM_BLOCKS 4096                         // (B/32)*(IN/32)
#define CMAT_BLOCKS  (OUT_SZ * (KTOT / 8) / 256)  // 2816

__global__ void kan_prep(const float* __restrict__ x,
                         const float* __restrict__ coeffs,
                         const float* __restrict__ bw) {
    if (blockIdx.x < PARAM_BLOCKS) {
        __shared__ float tile[32][33];
        const int pb = blockIdx.x;
        const int b0 = (pb & 255) * 32;
        const int i0 = (pb >> 8) * 32;
        const int tx = threadIdx.x & 31;
        const int ty = threadIdx.x >> 5;
#pragma unroll
        for (int r = ty; r < 32; r += 8)
            tile[r][tx] = x[(size_t)(b0 + r) * IN_SZ + i0 + tx];
        __syncthreads();
#pragma unroll
        for (int r = ty; r < 32; r += 8) {
            float xv = tile[tx][r];
            float xc = fminf(1.0f, fmaxf(-1.0f, xv));
            float s  = xc / (1.0f + __expf(-xc));
            float u  = (xc + 1.0f) * 10.0f;
            g_P[(size_t)(i0 + r) * B_SZ + b0 + tx] = make_float2(s, u);
        }
    } else {
        int gch = (blockIdx.x - PARAM_BLOCKS) * 256 + threadIdx.x;
        int o  = gch / (KTOT / 8);
        int ch = gch - o * (KTOT / 8);
        int k0 = ch * 8;
        __half h[8];
#pragma unroll
        for (int v = 0; v < 8; v++) {
            int k = k0 + v;
            int i = k / KPI;
            int j = k - i * KPI;
            float val = (j < GP1) ? coeffs[(size_t)o * (IN_SZ * GP1) + (size_t)i * GP1 + j]
                                  : bw[(size_t)o * IN_SZ + i];
            h[v] = __float2half_rn(val);
        }
        *(uint4*)(g_Cmat + (size_t)o * KTOT + k0) = *(const uint4*)h;
    }
}

// ---------------------------------------------------------------------------
// Main GEMM: 256 CTAs (64 b x 4 o), CTA tile 128x128, 8 warps (256 thr),
// warp tile 64x32.  Stage K=64, double buffered, one barrier per stage.
// SMEM: A[2][16KB] @0, B[2][16KB] @32768, P-ring[2][4KB] @65536 -> 72KB,
// 2 CTAs/SM.  Params arrive by cp.async at distance 2 (same groups as B);
// per-stage order: wait_group 0 ; bar ; genA(LDS)+loadB/loadP ; commit ; MMA.
// ---------------------------------------------------------------------------
#define A_REG  0
#define B_REG  32768
#define P_REG  65536
#define SMEM_SZ 73728

// genA (threads 0-127): row = one b; params read from the SMEM ring.
__device__ __forceinline__ void genA(char* smem, int buf, int stage, int row) {
    char* tile = smem + A_REG + buf * 16384;
    const char* pr = smem + P_REG + (stage & 1) * 4096;
    const uint32_t rowoff = (uint32_t)row * 128;
    uint4 z = make_uint4(0, 0, 0, 0);
#pragma unroll
    for (int c = 0; c < 8; c++)
        *(uint4*)(tile + sw128(rowoff + c * 16)) = z;

    const int k0   = stage * 64;
    const int i_lo = k0 / KPI;
#pragma unroll
    for (int f = 0; f < 4; f++) {
        int i = i_lo + f;
        if (i < IN_SZ) {
            float2 pv = *(const float2*)(pr + f * 1024 + row * 8);   // LDS.64
            int idx = (int)pv.y;                             // u >= 0
            idx = idx > 19 ? 19 : idx;                       // u==20 -> idx=19, t=1
            float t = pv.y - (float)idx;
            int kbase = i * KPI - k0;                        // stage-local slot 0
            int k1 = kbase + idx;                            // 1-t
            int k2 = k1 + 1;                                 // t
            int k3 = kbase + 21;                             // silu
            if ((unsigned)k1 < 64u)
                *(__half*)(tile + sw128(rowoff + (uint32_t)k1 * 2)) = __float2half_rn(1.0f - t);
            if ((unsigned)k2 < 64u)
                *(__half*)(tile + sw128(rowoff + (uint32_t)k2 * 2)) = __float2half_rn(t);
            if ((unsigned)k3 < 64u)
                *(__half*)(tile + sw128(rowoff + (uint32_t)k3 * 2)) = __float2half_rn(pv.x);
        }
    }
}

// loadB (threads 128-255): B tile for `stage` into buf, via cp.async.
__device__ __forceinline__ void loadB(uint32_t sb, int buf, int stage, int ob, int t2) {
    const int k0 = stage * 64;
#pragma unroll
    for (int rep = 0; rep < 8; rep++) {
        int q = t2 + rep * 128;
        int r = q >> 3;
        int c = q & 7;
        const __half* gp = g_Cmat + (size_t)(ob + r) * KTOT + (k0 + c * 8);
        uint32_t sa = sb + B_REG + buf * 16384 + sw128((uint32_t)r * 128 + (uint32_t)c * 16);
        asm volatile("cp.async.cg.shared.global [%0], [%1], 16;" :: "r"(sa), "l"(gp));
    }
}

// loadP (threads 128-255): params for `stage` (4 features x 128 float2 = 4KB)
// into ring slot stage&1.  2 chunks of 16B per thread.
__device__ __forceinline__ void loadP(uint32_t sb, int stage, int bb, int t2) {
    const int i_lo = (stage * 64) / KPI;
    const uint32_t dst0 = sb + P_REG + (uint32_t)(stage & 1) * 4096;
#pragma unroll
    for (int c = 0; c < 2; c++) {
        int q = t2 * 2 + c;          // 0..255
        int f = q >> 6;              // feature 0..3
        int w = q & 63;              // 16B unit within feature
        int i = i_lo + f;
        if (i < IN_SZ) {
            const float2* gp = g_P + (size_t)i * B_SZ + bb + w * 2;
            uint32_t sa = dst0 + (uint32_t)f * 1024 + (uint32_t)w * 16;
            asm volatile("cp.async.cg.shared.global [%0], [%1], 16;" :: "r"(sa), "l"(gp));
        }
    }
}

__global__ __launch_bounds__(256, 2) void kan_main(float* __restrict__ out) {
    extern __shared__ char smem[];
    uint32_t sb = smem_u32(smem);
    const int tid   = threadIdx.x;
    const int lane  = tid & 31;
    const int wid   = tid >> 5;
    const int warpM = wid >> 2;             // 0..1 -> 64-row b stripe
    const int warpN = wid & 3;              // 0..3 -> 32-col o stripe
    const int ob = blockIdx.x * 128, bb = blockIdx.y * 128;

    float acc[4][4][4];
#pragma unroll
    for (int mt = 0; mt < 4; mt++)
#pragma unroll
        for (int nt = 0; nt < 4; nt++)
#pragma unroll
            for (int v = 0; v < 4; v++) acc[mt][nt][v] = 0.f;

    const uint32_t lrow = lane & 15;
    const uint32_t lkb  = (lane >> 4) * 16;

    // prologue: P(0), P(1), B(0) in flight; then genA(0) from the ring.
    if (tid >= 128) {
        loadP(sb, 0, bb, tid - 128);
        loadP(sb, 1, bb, tid - 128);
        loadB(sb, 0, 0, ob, tid - 128);
    }
    asm volatile("cp.async.commit_group;");
    asm volatile("cp.async.wait_group 0;");
    __syncthreads();                              // P(0) visible to genA threads
    if (tid < 128) genA(smem, 0, 0, tid);

    for (int s = 0; s < STAGES; s++) {
        const int cb = s & 1, nb = cb ^ 1;

        asm volatile("cp.async.wait_group 0;");   // B(s) + P(s+1) complete
        __syncthreads();                          // visible; nb reads (s-1) done

        if (s + 1 < STAGES) {
            if (tid < 128) genA(smem, nb, s + 1, tid);          // pure LDS/STS
            else {
                loadB(sb, nb, s + 1, ob, tid - 128);
                if (s + 2 < STAGES) loadP(sb, s + 2, bb, tid - 128);
            }
            asm volatile("cp.async.commit_group;");
        }

        const uint32_t Ab = sb + A_REG + cb * 16384;
        const uint32_t Bb = sb + B_REG + cb * 16384;
#pragma unroll
        for (int ks = 0; ks < 4; ks++) {
            uint32_t a[4][4];
#pragma unroll
            for (int mt = 0; mt < 4; mt++) {
                uint32_t row = (uint32_t)(warpM * 64 + mt * 16) + lrow;
                ldsm_x4(Ab + sw128(row * 128 + ks * 32 + lkb), a[mt]);
            }
            uint32_t bf[2][4];
#pragma unroll
            for (int bt = 0; bt < 2; bt++) {
                uint32_t nrow = (uint32_t)(warpN * 32 + bt * 16) + lrow;
                ldsm_x4(Bb + sw128(nrow * 128 + ks * 32 + lkb), bf[bt]);
            }
#pragma unroll
            for (int mt = 0; mt < 4; mt++)
#pragma unroll
                for (int nt = 0; nt < 4; nt++) {
                    int bt = nt >> 1, hi = nt & 1;
                    mma16816(acc[mt][nt], a[mt], bf[bt][hi], bf[bt][hi + 2]);
                }
        }
    }

    // epilogue: direct f32 stores
#pragma unroll
    for (int mt = 0; mt < 4; mt++) {
        int r0 = bb + warpM * 64 + mt * 16 + (lane >> 2);
#pragma unroll
        for (int nt = 0; nt < 4; nt++) {
            int c0 = ob + warpN * 32 + nt * 8 + (lane & 3) * 2;
            *(float2*)&out[(size_t)r0 * OUT_SZ + c0] =
                make_float2(acc[mt][nt][0], acc[mt][nt][1]);
            *(float2*)&out[(size_t)(r0 + 8) * OUT_SZ + c0] =
                make_float2(acc[mt][nt][2], acc[mt][nt][3]);
        }
    }
}

// ---------------------------------------------------------------------------
// Launch: x [8192,512], coeffs [512,512,21], base_w [512,512] -> out f32 [8192,512]
// ---------------------------------------------------------------------------
extern "C" void kernel_launch(void* const* d_in, const int* in_sizes, int n_in,
                              void* d_out, int out_size) {
    const float* x      = (const float*)d_in[0];
    const float* coeffs = (const float*)d_in[1];
    const float* base_w = (const float*)d_in[2];
    float* out = (float*)d_out;

    cudaFuncSetAttribute(kan_main, cudaFuncAttributeMaxDynamicSharedMemorySize, SMEM_SZ);

    kan_prep<<<PARAM_BLOCKS + CMAT_BLOCKS, 256>>>(x, coeffs, base_w);
    kan_main<<<dim3(OUT_SZ / 128, B_SZ / 128), 256, SMEM_SZ>>>(out);
}